// round 5
// baseline (speedup 1.0000x reference)
#include <cuda_runtime.h>
#include <cuda_bf16.h>
#include <math.h>
#include <stdint.h>

// Problem constants
#define N_ROWS   512
#define N_CAMS   8
#define M_PER    2048
#define D_FULL   4096
#define K_HALF   2048
#define P_TOT    16384
#define TOPK     54
#define INV_BETA 20.0f

// ---------------- scratch (device globals) ------------------------------------
__device__ float g_sims[2ull * N_ROWS * P_TOT];                 // 64 MB
__device__ float g_loss[2 * N_ROWS * 3];
__device__ __nv_bfloat16 g_featB[(size_t)N_ROWS * D_FULL];      // 4 MB
__device__ __nv_bfloat16 g_memB[(size_t)P_TOT * D_FULL];        // 128 MB

// ---------------- helpers ------------------------------------------------------
__device__ __forceinline__ uint32_t smem_u32(const void* p) {
    uint32_t a;
    asm("{ .reg .u64 t; cvta.to.shared.u64 t, %1; cvt.u32.u64 %0, t; }"
        : "=r"(a) : "l"(p));
    return a;
}
__device__ __forceinline__ void cp16(uint32_t s, const void* g) {
    asm volatile("cp.async.cg.shared.global [%0], [%1], 16;" :: "r"(s), "l"(g));
}
#define CP_COMMIT() asm volatile("cp.async.commit_group;" ::: "memory")

__device__ __forceinline__ void mma16(float* d, const uint32_t* a,
                                      uint32_t b0, uint32_t b1) {
    asm volatile(
        "mma.sync.aligned.m16n8k16.row.col.f32.bf16.bf16.f32 "
        "{%0,%1,%2,%3}, {%4,%5,%6,%7}, {%8,%9}, {%0,%1,%2,%3};"
        : "+f"(d[0]), "+f"(d[1]), "+f"(d[2]), "+f"(d[3])
        : "r"(a[0]), "r"(a[1]), "r"(a[2]), "r"(a[3]), "r"(b0), "r"(b1));
}

// ---------------- fp32 -> bf16 conversion --------------------------------------
__global__ void convA_k(const float* __restrict__ f) {
    size_t i = (size_t)blockIdx.x * 256 + threadIdx.x;
    float4 v = ((const float4*)f)[i];
    __nv_bfloat162 p0 = __floats2bfloat162_rn(v.x, v.y);
    __nv_bfloat162 p1 = __floats2bfloat162_rn(v.z, v.w);
    uint2 o; o.x = *(uint32_t*)&p0; o.y = *(uint32_t*)&p1;
    ((uint2*)g_featB)[i] = o;
}
__global__ void convB_k(const float* __restrict__ m) {
    size_t i = (size_t)blockIdx.x * 256 + threadIdx.x;
    float4 v = ((const float4*)m)[i];
    __nv_bfloat162 p0 = __floats2bfloat162_rn(v.x, v.y);
    __nv_bfloat162 p1 = __floats2bfloat162_rn(v.z, v.w);
    uint2 o; o.x = *(uint32_t*)&p0; o.y = *(uint32_t*)&p1;
    ((uint2*)g_memB)[i] = o;
}

// ---------------- bf16 mma.sync GEMM: 128x128 tile, 4-stage ring ---------------
#define GBK      32
#define NSTG     (K_HALF / GBK)     // 64
#define STG_B    20480u
#define ROWB     80u

__device__ __forceinline__ void load_stage(int st, int tid, int mtile, int ntile,
                                           int h, uint32_t sbase) {
    const uint32_t buf = sbase + (uint32_t)(st & 3) * STG_B;
    const int kg = h * K_HALF + st * GBK;
#pragma unroll
    for (int i = 0; i < 2; i++) {
        int idx = tid + i * 256;
        int r = idx >> 2, ch = idx & 3;
        cp16(buf + (uint32_t)r * ROWB + (uint32_t)ch * 16,
             g_featB + (size_t)(mtile * 128 + r) * D_FULL + kg + ch * 8);
    }
#pragma unroll
    for (int i = 0; i < 2; i++) {
        int idx = tid + i * 256;
        int r = idx >> 2, ch = idx & 3;
        cp16(buf + 10240u + (uint32_t)r * ROWB + (uint32_t)ch * 16,
             g_memB + (size_t)(ntile * 128 + r) * D_FULL + kg + ch * 8);
    }
    CP_COMMIT();
}

__global__ void __launch_bounds__(256, 2)
gemm_mma(void) {
    extern __shared__ char sm[];
    const uint32_t sbase = smem_u32(sm);

    const int tid = threadIdx.x;
    const int bx = blockIdx.x;
    const int h  = blockIdx.y;
    const int ntile = bx >> 2;
    const int mtile = bx & 3;

    const int w  = tid >> 5;
    const int l  = tid & 31;
    const int wm = (w & 3) * 32;
    const int wn = (w >> 2) * 64;
    const int g  = l >> 2;
    const int tg = l & 3;

    float acc[2][8][4];
#pragma unroll
    for (int mi = 0; mi < 2; mi++)
#pragma unroll
        for (int ni = 0; ni < 8; ni++)
#pragma unroll
            for (int c = 0; c < 4; c++) acc[mi][ni][c] = 0.0f;

    load_stage(0, tid, mtile, ntile, h, sbase);
    load_stage(1, tid, mtile, ntile, h, sbase);
    load_stage(2, tid, mtile, ntile, h, sbase);

    for (int st = 0; st < NSTG; st++) {
        if (st < NSTG - 2)       asm volatile("cp.async.wait_group 2;" ::: "memory");
        else if (st == NSTG - 2) asm volatile("cp.async.wait_group 1;" ::: "memory");
        else                     asm volatile("cp.async.wait_group 0;" ::: "memory");
        __syncthreads();

        // issue next load first (buffer (st+3)&3 was consumed at stage st-1)
        if (st + 3 < NSTG) load_stage(st + 3, tid, mtile, ntile, h, sbase);

        const char* base = sm + (size_t)(st & 3) * STG_B;
#pragma unroll
        for (int ks = 0; ks < 2; ks++) {
            const int kb = ks * 32;
            uint32_t a[2][4];
#pragma unroll
            for (int mi = 0; mi < 2; mi++) {
                const char* ar = base + (wm + mi * 16 + g) * ROWB + kb + tg * 4;
                a[mi][0] = *(const uint32_t*)(ar);
                a[mi][1] = *(const uint32_t*)(ar + 8 * ROWB);
                a[mi][2] = *(const uint32_t*)(ar + 16);
                a[mi][3] = *(const uint32_t*)(ar + 8 * ROWB + 16);
            }
#pragma unroll
            for (int ni = 0; ni < 8; ni++) {
                const char* br = base + 10240 + (wn + ni * 8 + g) * ROWB + kb + tg * 4;
                uint32_t b0 = *(const uint32_t*)(br);
                uint32_t b1 = *(const uint32_t*)(br + 16);
                mma16(acc[0][ni], a[0], b0, b1);
                mma16(acc[1][ni], a[1], b0, b1);
            }
        }
    }

    const int colbase = ntile * 128 + wn;
#pragma unroll
    for (int mi = 0; mi < 2; mi++) {
        const int row = mtile * 128 + wm + mi * 16 + g;
        float* d0 = g_sims + ((size_t)(h * N_ROWS + row)) * P_TOT + colbase + tg * 2;
        float* d1 = d0 + (size_t)8 * P_TOT;
#pragma unroll
        for (int ni = 0; ni < 8; ni++) {
            *(float2*)(d0 + ni * 8) = make_float2(acc[mi][ni][0], acc[mi][ni][1]);
            *(float2*)(d1 + ni * 8) = make_float2(acc[mi][ni][2], acc[mi][ni][3]);
        }
    }
}

// ---------------- per-row loss reduction ----------------------------------------
// 512 threads; thread owns contiguous 32 elems (within one cam block).
__device__ __forceinline__ uint32_t fkey(float v) {
    uint32_t u = __float_as_uint(v);
    return u ^ (uint32_t)(((int32_t)u >> 31) | 0x80000000);
}

__global__ void __launch_bounds__(512, 3)
reduce_kernel(const int* __restrict__ cams, const int* __restrict__ proxy)
{
    extern __shared__ float sh[];
    float* row = sh;                       // 16384 floats

    __shared__ int   hist1[256];
    __shared__ int   hist2[256];
    __shared__ float wmax[16];
    __shared__ int   widx[16];
    __shared__ float red[16];
    __shared__ float candv[512];
    __shared__ int   candi[512];
    __shared__ float camMax[N_CAMS];
    __shared__ int   camIdx[N_CAMS];
    __shared__ float topv[TOPK];
    __shared__ int   topi[TOPK];
    __shared__ float lse_buf[56];
    __shared__ float s_ce;
    __shared__ int   s_b1, s_above, s_count;
    __shared__ uint32_t s_thr;

    const int n = blockIdx.x;
    const int h = blockIdx.y;
    const int tid = threadIdx.x;
    const int w = tid >> 5, l = tid & 31;
    const int base = tid * 32;             // contiguous chunk

    if (tid < 256) { hist1[tid] = 0; hist2[tid] = 0; }
    if (tid == 0) s_count = 0;
    __syncthreads();

    const int c = cams[n];
    const int p = proxy[n];

    // ---- pass 1: load + chunk argmax + 8-bit histogram ----
    const float* src = g_sims + ((size_t)h * N_ROWS + n) * P_TOT;
    float bv = -3.0e38f; int bi = base;
#pragma unroll
    for (int j0 = 0; j0 < 32; j0 += 4) {
        float4 v = ((const float4*)src)[(base + j0) >> 2];
        ((float4*)row)[(base + j0) >> 2] = v;
        if (v.x > bv) { bv = v.x; bi = base + j0; }
        if (v.y > bv) { bv = v.y; bi = base + j0 + 1; }
        if (v.z > bv) { bv = v.z; bi = base + j0 + 2; }
        if (v.w > bv) { bv = v.w; bi = base + j0 + 3; }
        atomicAdd(&hist1[fkey(v.x) >> 24], 1);
        atomicAdd(&hist1[fkey(v.y) >> 24], 1);
        atomicAdd(&hist1[fkey(v.z) >> 24], 1);
        atomicAdd(&hist1[fkey(v.w) >> 24], 1);
    }
#pragma unroll
    for (int o = 16; o > 0; o >>= 1) {
        float ov = __shfl_down_sync(0xffffffffu, bv, o);
        int   oi = __shfl_down_sync(0xffffffffu, bi, o);
        if (ov > bv || (ov == bv && oi < bi)) { bv = ov; bi = oi; }
    }
    if (l == 0) { wmax[w] = bv; widx[w] = bi; }   // warp w covers cam w>>1
    __syncthreads();

    // ---- cam maxima + first radix digit (parallel small jobs) ----
    if (tid < N_CAMS) {
        float a = wmax[2 * tid]; int ai = widx[2 * tid];
        float b2 = wmax[2 * tid + 1]; int bi2 = widx[2 * tid + 1];
        if (b2 > a || (b2 == a && bi2 < ai)) { a = b2; ai = bi2; }
        camMax[tid] = a; camIdx[tid] = ai;
    }
    if (tid == 32) {
        int cum = 0, b = 255;
        for (; b >= 0; b--) { cum += hist1[b]; if (cum >= TOPK) break; }
        s_b1 = b; s_above = cum - hist1[b];
    }
    __syncthreads();

    // ---- pass 2 (smem): second digit histogram + CE sum-exp ----
    const uint32_t b1 = (uint32_t)s_b1;
    const float bm = camMax[c];
    const int mycam = base >> 11;
    float ssum = 0.0f;
#pragma unroll
    for (int j = 0; j < 32; j++) {
        float v = row[base + j];
        uint32_t k = fkey(v);
        if ((k >> 24) == b1) atomicAdd(&hist2[(k >> 16) & 0xFF], 1);
        if (mycam == c) ssum += expf((v - bm) * INV_BETA);
    }
#pragma unroll
    for (int o = 16; o > 0; o >>= 1) ssum += __shfl_down_sync(0xffffffffu, ssum, o);
    if (l == 0) red[w] = ssum;
    __syncthreads();

    if (tid == 0) {
        int cum = s_above, b = 255;
        for (; b >= 0; b--) { cum += hist2[b]; if (cum >= TOPK) break; }
        s_thr = (b1 << 24) | ((uint32_t)b << 16);
        float tot = 0.0f;
        for (int i = 0; i < 16; i++) tot += red[i];
        s_ce = bm * INV_BETA + logf(tot) - row[p] * INV_BETA;
    }
    __syncthreads();

    // ---- pass 3 (smem): gather candidates >= threshold ----
    const uint32_t thr = s_thr;
#pragma unroll
    for (int j = 0; j < 32; j++) {
        float v = row[base + j];
        if (fkey(v) >= thr) {
            int k = atomicAdd(&s_count, 1);
            if (k < 512) { candv[k] = v; candi[k] = base + j; }
        }
    }
    __syncthreads();

    // ---- warp 0: exact top-54 + both lse tails ----
    if (w == 0) {
        const int nc = (s_count < 512) ? s_count : 512;
        for (int it = 0; it < TOPK; it++) {
            float tv = -3.0e38f; int ti = 0x7FFFFFFF;
            for (int k = l; k < nc; k += 32) {
                float v = candv[k]; int ii = candi[k];
                if (v > tv || (v == tv && ii < ti)) { tv = v; ti = ii; }
            }
#pragma unroll
            for (int o = 16; o > 0; o >>= 1) {
                float ov = __shfl_down_sync(0xffffffffu, tv, o);
                int   oi = __shfl_down_sync(0xffffffffu, ti, o);
                if (ov > tv || (ov == tv && oi < ti)) { tv = ov; ti = oi; }
            }
            tv = __shfl_sync(0xffffffffu, tv, 0);
            ti = __shfl_sync(0xffffffffu, ti, 0);
            if (l == 0) { topv[it] = tv; topi[it] = ti; }
            for (int k = l; k < nc; k += 32)
                if (candi[k] == ti) candv[k] = -3.0e38f;
            __syncwarp();
        }

        // assoc list (lane 0 builds; topv is descending)
        if (l == 0) {
            const float pos = row[p] * INV_BETA;
            lse_buf[0] = pos;
            int cnt = 1;
            for (int it = 0; it < TOPK && cnt < 51; it++) {
                if (topi[it] == p) continue;
                lse_buf[cnt++] = topv[it] * INV_BETA;
            }
        }
        __syncwarp();
        {
            const float pos = lse_buf[0];
            const float m1 = fmaxf(pos, lse_buf[1]);
            float e = 0.0f;
            if (l < 51) e += expf(lse_buf[l] - m1);
            if (l + 32 < 51) e += expf(lse_buf[l + 32] - m1);
#pragma unroll
            for (int o = 16; o > 0; o >>= 1) e += __shfl_down_sync(0xffffffffu, e, o);
            if (l == 0) {
                float assoc = m1 + logf(e) - pos;
                g_loss[((size_t)h * N_ROWS + n) * 3 + 1] = assoc;
            }
        }
        __syncwarp();

        // online list
        if (l == 0) {
            int o0 = 0;
            for (int cc = 1; cc < N_CAMS; cc++) if (camMax[cc] > camMax[o0]) o0 = cc;
            int o1 = -1;
            for (int cc = 0; cc < N_CAMS; cc++) {
                if (cc == o0) continue;
                if (o1 < 0 || camMax[cc] > camMax[o1]) o1 = cc;
            }
            int o2 = -1;
            for (int cc = 0; cc < N_CAMS; cc++) {
                if (cc == o0 || cc == o1) continue;
                if (o2 < 0 || camMax[cc] > camMax[o2]) o2 = cc;
            }
            const int ex0 = camIdx[o0], ex1 = camIdx[o1], ex2 = camIdx[o2];
            lse_buf[0] = camMax[o0] * INV_BETA;
            lse_buf[1] = camMax[o1] * INV_BETA;
            lse_buf[2] = camMax[o2] * INV_BETA;
            int oc = 3;
            for (int it = 0; it < TOPK && oc < 33; it++) {
                const int idx = topi[it];
                if (idx == ex0 || idx == ex1 || idx == ex2) continue;
                lse_buf[oc++] = topv[it] * INV_BETA;
            }
        }
        __syncwarp();
        {
            const float l0 = lse_buf[0], l1 = lse_buf[1], l2 = lse_buf[2];
            const float m2 = l0;          // global max dominates the list
            float e = 0.0f;
            if (l < 33) e += expf(lse_buf[l] - m2);
            if (l == 0) e += expf(lse_buf[32] - m2);
#pragma unroll
            for (int o = 16; o > 0; o >>= 1) e += __shfl_down_sync(0xffffffffu, e, o);
            if (l == 0) {
                float online = m2 + logf(e) - (l0 + l1 + l2) * (1.0f / 3.0f);
                float* dst = g_loss + ((size_t)h * N_ROWS + n) * 3;
                dst[0] = s_ce;
                dst[2] = online;
            }
        }
    }
}

// ---------------- final deterministic weighted sum -------------------------------
__global__ void final_kernel(const int* __restrict__ cams, float* __restrict__ out)
{
    __shared__ double sd[N_ROWS];
    __shared__ int scams[N_ROWS];
    const int n = threadIdx.x;
    scams[n] = cams[n];
    __syncthreads();
    const int c = scams[n];
    int cnt = 0;
    for (int i = 0; i < N_ROWS; i++) cnt += (scams[i] == c);
    const double w = 1.0 / (double)cnt;
    const float* a = g_loss + (size_t)n * 3;
    const float* b = g_loss + (size_t)(N_ROWS + n) * 3;
    double t = 0.6 * ((double)a[0] + (double)b[0])
             + 0.7 * ((double)a[1] + (double)b[1])
             + 0.7 * ((double)a[2] + (double)b[2]);
    sd[n] = t * w;
    __syncthreads();
    for (int s = 256; s > 0; s >>= 1) {
        if (n < s) sd[n] += sd[n + s];
        __syncthreads();
    }
    if (n == 0) out[0] = (float)sd[0];
}

// ---------------- entry -----------------------------------------------------------
extern "C" void kernel_launch(void* const* d_in, const int* in_sizes, int n_in,
                              void* d_out, int out_size)
{
    const float* features = (const float*)d_in[0];
    const float* memory = (const float*)d_in[2];
    const int* cams  = (const int*)d_in[3];
    const int* proxy = (const int*)d_in[4];
    float* out = (float*)d_out;

    convA_k<<<(N_ROWS * D_FULL / 4) / 256, 256>>>(features);
    convB_k<<<((size_t)P_TOT * D_FULL / 4) / 256, 256>>>(memory);

    const int gsmem = 4 * (int)STG_B;   // 81920
    cudaFuncSetAttribute(gemm_mma, cudaFuncAttributeMaxDynamicSharedMemorySize, gsmem);
    dim3 ggrid(512, 2);
    gemm_mma<<<ggrid, 256, gsmem>>>();

    const int smem_bytes = P_TOT * (int)sizeof(float);
    cudaFuncSetAttribute(reduce_kernel, cudaFuncAttributeMaxDynamicSharedMemorySize,
                         smem_bytes);
    dim3 rgrid(N_ROWS, 2);
    reduce_kernel<<<rgrid, 512, smem_bytes>>>(cams, proxy);

    final_kernel<<<1, N_ROWS>>>(cams, out);
}

// round 6
// speedup vs baseline: 1.2806x; 1.2806x over previous
#include <cuda_runtime.h>
#include <cuda_bf16.h>
#include <math.h>
#include <stdint.h>

// Problem constants
#define N_ROWS   512
#define N_CAMS   8
#define M_PER    2048
#define D_FULL   4096
#define K_HALF   2048
#define P_TOT    16384
#define TOPK     54
#define INV_BETA 20.0f

// ---------------- scratch (device globals) ------------------------------------
__device__ float g_sims[2ull * N_ROWS * P_TOT];                 // 64 MB
__device__ float g_loss[2 * N_ROWS * 3];
__device__ __nv_bfloat16 g_featB[(size_t)N_ROWS * D_FULL];      // 4 MB
__device__ __nv_bfloat16 g_memB[(size_t)P_TOT * D_FULL];        // 128 MB

// ---------------- helpers ------------------------------------------------------
__device__ __forceinline__ uint32_t smem_u32(const void* p) {
    uint32_t a;
    asm("{ .reg .u64 t; cvta.to.shared.u64 t, %1; cvt.u32.u64 %0, t; }"
        : "=r"(a) : "l"(p));
    return a;
}
__device__ __forceinline__ void cp16(uint32_t s, const void* g) {
    asm volatile("cp.async.cg.shared.global [%0], [%1], 16;" :: "r"(s), "l"(g));
}
#define CP_COMMIT() asm volatile("cp.async.commit_group;" ::: "memory")

__device__ __forceinline__ void mma16(float* d, const uint32_t* a,
                                      uint32_t b0, uint32_t b1) {
    asm volatile(
        "mma.sync.aligned.m16n8k16.row.col.f32.bf16.bf16.f32 "
        "{%0,%1,%2,%3}, {%4,%5,%6,%7}, {%8,%9}, {%0,%1,%2,%3};"
        : "+f"(d[0]), "+f"(d[1]), "+f"(d[2]), "+f"(d[3])
        : "r"(a[0]), "r"(a[1]), "r"(a[2]), "r"(a[3]), "r"(b0), "r"(b1));
}

// ---------------- fp32 -> bf16 conversion --------------------------------------
__global__ void convA_k(const float* __restrict__ f) {
    size_t i = (size_t)blockIdx.x * 256 + threadIdx.x;
    float4 v = ((const float4*)f)[i];
    __nv_bfloat162 p0 = __floats2bfloat162_rn(v.x, v.y);
    __nv_bfloat162 p1 = __floats2bfloat162_rn(v.z, v.w);
    uint2 o; o.x = *(uint32_t*)&p0; o.y = *(uint32_t*)&p1;
    ((uint2*)g_featB)[i] = o;
}
__global__ void convB_k(const float* __restrict__ m) {
    size_t i = (size_t)blockIdx.x * 256 + threadIdx.x;
    float4 v = ((const float4*)m)[i];
    __nv_bfloat162 p0 = __floats2bfloat162_rn(v.x, v.y);
    __nv_bfloat162 p1 = __floats2bfloat162_rn(v.z, v.w);
    uint2 o; o.x = *(uint32_t*)&p0; o.y = *(uint32_t*)&p1;
    ((uint2*)g_memB)[i] = o;
}

// ---------------- bf16 mma.sync GEMM: 128x128 tile, 4-stage ring ---------------
#define GBK      32
#define NSTG     (K_HALF / GBK)     // 64
#define STG_B    20480u
#define ROWB     80u

__device__ __forceinline__ void load_stage(int st, int tid, int mtile, int ntile,
                                           int h, uint32_t sbase) {
    const uint32_t buf = sbase + (uint32_t)(st & 3) * STG_B;
    const int kg = h * K_HALF + st * GBK;
#pragma unroll
    for (int i = 0; i < 2; i++) {
        int idx = tid + i * 256;
        int r = idx >> 2, ch = idx & 3;
        cp16(buf + (uint32_t)r * ROWB + (uint32_t)ch * 16,
             g_featB + (size_t)(mtile * 128 + r) * D_FULL + kg + ch * 8);
    }
#pragma unroll
    for (int i = 0; i < 2; i++) {
        int idx = tid + i * 256;
        int r = idx >> 2, ch = idx & 3;
        cp16(buf + 10240u + (uint32_t)r * ROWB + (uint32_t)ch * 16,
             g_memB + (size_t)(ntile * 128 + r) * D_FULL + kg + ch * 8);
    }
    CP_COMMIT();
}

__global__ void __launch_bounds__(256, 2)
gemm_mma(void) {
    extern __shared__ char sm[];
    const uint32_t sbase = smem_u32(sm);

    const int tid = threadIdx.x;
    const int bx = blockIdx.x;
    const int h  = blockIdx.y;
    const int ntile = bx >> 2;
    const int mtile = bx & 3;

    const int w  = tid >> 5;
    const int l  = tid & 31;
    const int wm = (w & 3) * 32;
    const int wn = (w >> 2) * 64;
    const int g  = l >> 2;
    const int tg = l & 3;

    float acc[2][8][4];
#pragma unroll
    for (int mi = 0; mi < 2; mi++)
#pragma unroll
        for (int ni = 0; ni < 8; ni++)
#pragma unroll
            for (int c = 0; c < 4; c++) acc[mi][ni][c] = 0.0f;

    load_stage(0, tid, mtile, ntile, h, sbase);
    load_stage(1, tid, mtile, ntile, h, sbase);
    load_stage(2, tid, mtile, ntile, h, sbase);

    for (int st = 0; st < NSTG; st++) {
        if (st < NSTG - 2)       asm volatile("cp.async.wait_group 2;" ::: "memory");
        else if (st == NSTG - 2) asm volatile("cp.async.wait_group 1;" ::: "memory");
        else                     asm volatile("cp.async.wait_group 0;" ::: "memory");
        __syncthreads();

        if (st + 3 < NSTG) load_stage(st + 3, tid, mtile, ntile, h, sbase);

        const char* base = sm + (size_t)(st & 3) * STG_B;
#pragma unroll
        for (int ks = 0; ks < 2; ks++) {
            const int kb = ks * 32;
            uint32_t a[2][4];
#pragma unroll
            for (int mi = 0; mi < 2; mi++) {
                const char* ar = base + (wm + mi * 16 + g) * ROWB + kb + tg * 4;
                a[mi][0] = *(const uint32_t*)(ar);
                a[mi][1] = *(const uint32_t*)(ar + 8 * ROWB);
                a[mi][2] = *(const uint32_t*)(ar + 16);
                a[mi][3] = *(const uint32_t*)(ar + 8 * ROWB + 16);
            }
#pragma unroll
            for (int ni = 0; ni < 8; ni++) {
                const char* br = base + 10240 + (wn + ni * 8 + g) * ROWB + kb + tg * 4;
                uint32_t b0 = *(const uint32_t*)(br);
                uint32_t b1 = *(const uint32_t*)(br + 16);
                mma16(acc[0][ni], a[0], b0, b1);
                mma16(acc[1][ni], a[1], b0, b1);
            }
        }
    }

    const int colbase = ntile * 128 + wn;
#pragma unroll
    for (int mi = 0; mi < 2; mi++) {
        const int row = mtile * 128 + wm + mi * 16 + g;
        float* d0 = g_sims + ((size_t)(h * N_ROWS + row)) * P_TOT + colbase + tg * 2;
        float* d1 = d0 + (size_t)8 * P_TOT;
#pragma unroll
        for (int ni = 0; ni < 8; ni++) {
            *(float2*)(d0 + ni * 8) = make_float2(acc[mi][ni][0], acc[mi][ni][1]);
            *(float2*)(d1 + ni * 8) = make_float2(acc[mi][ni][2], acc[mi][ni][3]);
        }
    }
}

// ---------------- per-row loss reduction ----------------------------------------
__device__ __forceinline__ uint32_t fkey(float v) {
    uint32_t u = __float_as_uint(v);
    return u ^ (uint32_t)(((int32_t)u >> 31) | 0x80000000);
}

__global__ void __launch_bounds__(512, 3)
reduce_kernel(const int* __restrict__ cams, const int* __restrict__ proxy)
{
    extern __shared__ float sh[];
    float* row = sh;                         // 16384 floats
    float4* row4 = (float4*)sh;

    __shared__ int   hist1[256];
    __shared__ int   hist2[256];
    __shared__ float wmax[16];
    __shared__ int   widx[16];
    __shared__ float red[16];
    __shared__ float candv[512];
    __shared__ int   candi[512];
    __shared__ float camMax[N_CAMS];
    __shared__ int   camIdx[N_CAMS];
    __shared__ float topv[TOPK];
    __shared__ int   topi[TOPK];
    __shared__ float lse_buf[56];
    __shared__ float s_ce;
    __shared__ int   s_b1, s_above, s_count;
    __shared__ uint32_t s_thr;

    const int n = blockIdx.x;
    const int h = blockIdx.y;
    const int tid = threadIdx.x;
    const int w = tid >> 5, l = tid & 31;

    if (tid < 256) { hist1[tid] = 0; hist2[tid] = 0; }
    if (tid == 0) s_count = 0;
    __syncthreads();

    const int c = cams[n];
    const int p = proxy[n];

    // ---- pass 1: coalesced load + per-cam argmax + warp-aggregated histogram ----
    // warp w covers cam (w>>1), half (w&1): 256 consecutive float4s.
    const float4* src4 = (const float4*)(g_sims + ((size_t)h * N_ROWS + n) * P_TOT);
    const int f4base = (w >> 1) * 512 + (w & 1) * 256;
    float bv = -3.0e38f; int bi = f4base * 4;
#pragma unroll
    for (int s = 0; s < 8; s++) {
        const int f4 = f4base + s * 32 + l;
        float4 v = src4[f4];
        row4[f4] = v;
        const int j = f4 * 4;
        if (v.x > bv) { bv = v.x; bi = j; }
        if (v.y > bv) { bv = v.y; bi = j + 1; }
        if (v.z > bv) { bv = v.z; bi = j + 2; }
        if (v.w > bv) { bv = v.w; bi = j + 3; }
        // warp-aggregated histogram adds (all lanes active)
        float comp[4] = {v.x, v.y, v.z, v.w};
#pragma unroll
        for (int q = 0; q < 4; q++) {
            uint32_t b = fkey(comp[q]) >> 24;
            unsigned m = __match_any_sync(0xffffffffu, b);
            if ((m & ((1u << l) - 1u)) == 0) atomicAdd(&hist1[b], __popc(m));
        }
    }
#pragma unroll
    for (int o = 16; o > 0; o >>= 1) {
        float ov = __shfl_down_sync(0xffffffffu, bv, o);
        int   oi = __shfl_down_sync(0xffffffffu, bi, o);
        if (ov > bv || (ov == bv && oi < bi)) { bv = ov; bi = oi; }
    }
    if (l == 0) { wmax[w] = bv; widx[w] = bi; }
    __syncthreads();

    // ---- cam maxima + first radix digit ----
    if (tid < N_CAMS) {
        float a = wmax[2 * tid]; int ai = widx[2 * tid];
        float b2 = wmax[2 * tid + 1]; int bi2 = widx[2 * tid + 1];
        if (b2 > a || (b2 == a && bi2 < ai)) { a = b2; ai = bi2; }
        camMax[tid] = a; camIdx[tid] = ai;
    }
    if (tid == 32) {
        int cum = 0, b = 255;
        for (; b >= 0; b--) { cum += hist1[b]; if (cum >= TOPK) break; }
        s_b1 = b; s_above = cum - hist1[b];
    }
    __syncthreads();

    // ---- pass 2: second-digit histogram + CE sum-exp (strided, conflict-free) ----
    const uint32_t b1 = (uint32_t)s_b1;
    const float bm = camMax[c];
    float ssum = 0.0f;
#pragma unroll
    for (int s = 0; s < 8; s++) {
        const int f4 = tid + s * 512;
        float4 v = row4[f4];
        float comp[4] = {v.x, v.y, v.z, v.w};
#pragma unroll
        for (int q = 0; q < 4; q++) {
            uint32_t k = fkey(comp[q]);
            if ((k >> 24) == b1) atomicAdd(&hist2[(k >> 16) & 0xFF], 1);
        }
        if (s == c) {   // float4s of cam block c are exactly iteration s==c
            ssum += expf((v.x - bm) * INV_BETA) + expf((v.y - bm) * INV_BETA)
                  + expf((v.z - bm) * INV_BETA) + expf((v.w - bm) * INV_BETA);
        }
    }
#pragma unroll
    for (int o = 16; o > 0; o >>= 1) ssum += __shfl_down_sync(0xffffffffu, ssum, o);
    if (l == 0) red[w] = ssum;
    __syncthreads();

    if (tid == 0) {
        int cum = s_above, b = 255;
        for (; b >= 0; b--) { cum += hist2[b]; if (cum >= TOPK) break; }
        s_thr = (b1 << 24) | ((uint32_t)b << 16);
        float tot = 0.0f;
        for (int i = 0; i < 16; i++) tot += red[i];
        s_ce = bm * INV_BETA + logf(tot) - row[p] * INV_BETA;
    }
    __syncthreads();

    // ---- pass 3: gather candidates >= threshold (strided) ----
    const uint32_t thr = s_thr;
#pragma unroll
    for (int s = 0; s < 8; s++) {
        const int f4 = tid + s * 512;
        float4 v = row4[f4];
        float comp[4] = {v.x, v.y, v.z, v.w};
#pragma unroll
        for (int q = 0; q < 4; q++) {
            if (fkey(comp[q]) >= thr) {
                int k = atomicAdd(&s_count, 1);
                if (k < 512) { candv[k] = comp[q]; candi[k] = f4 * 4 + q; }
            }
        }
    }
    __syncthreads();

    // ---- warp 0: exact top-54 + both lse tails ----
    if (w == 0) {
        const int nc = (s_count < 512) ? s_count : 512;
        for (int it = 0; it < TOPK; it++) {
            float tv = -3.0e38f; int ti = 0x7FFFFFFF;
            for (int k = l; k < nc; k += 32) {
                float v = candv[k]; int ii = candi[k];
                if (v > tv || (v == tv && ii < ti)) { tv = v; ti = ii; }
            }
#pragma unroll
            for (int o = 16; o > 0; o >>= 1) {
                float ov = __shfl_down_sync(0xffffffffu, tv, o);
                int   oi = __shfl_down_sync(0xffffffffu, ti, o);
                if (ov > tv || (ov == tv && oi < ti)) { tv = ov; ti = oi; }
            }
            tv = __shfl_sync(0xffffffffu, tv, 0);
            ti = __shfl_sync(0xffffffffu, ti, 0);
            if (l == 0) { topv[it] = tv; topi[it] = ti; }
            for (int k = l; k < nc; k += 32)
                if (candi[k] == ti) candv[k] = -3.0e38f;
            __syncwarp();
        }

        // assoc list (topv descending)
        if (l == 0) {
            const float pos = row[p] * INV_BETA;
            lse_buf[0] = pos;
            int cnt = 1;
            for (int it = 0; it < TOPK && cnt < 51; it++) {
                if (topi[it] == p) continue;
                lse_buf[cnt++] = topv[it] * INV_BETA;
            }
        }
        __syncwarp();
        {
            const float pos = lse_buf[0];
            const float m1 = fmaxf(pos, lse_buf[1]);
            float e = 0.0f;
            if (l < 51) e += expf(lse_buf[l] - m1);
            if (l + 32 < 51) e += expf(lse_buf[l + 32] - m1);
#pragma unroll
            for (int o = 16; o > 0; o >>= 1) e += __shfl_down_sync(0xffffffffu, e, o);
            if (l == 0)
                g_loss[((size_t)h * N_ROWS + n) * 3 + 1] = m1 + logf(e) - pos;
        }
        __syncwarp();

        // online list
        if (l == 0) {
            int o0 = 0;
            for (int cc = 1; cc < N_CAMS; cc++) if (camMax[cc] > camMax[o0]) o0 = cc;
            int o1 = -1;
            for (int cc = 0; cc < N_CAMS; cc++) {
                if (cc == o0) continue;
                if (o1 < 0 || camMax[cc] > camMax[o1]) o1 = cc;
            }
            int o2 = -1;
            for (int cc = 0; cc < N_CAMS; cc++) {
                if (cc == o0 || cc == o1) continue;
                if (o2 < 0 || camMax[cc] > camMax[o2]) o2 = cc;
            }
            const int ex0 = camIdx[o0], ex1 = camIdx[o1], ex2 = camIdx[o2];
            lse_buf[0] = camMax[o0] * INV_BETA;
            lse_buf[1] = camMax[o1] * INV_BETA;
            lse_buf[2] = camMax[o2] * INV_BETA;
            int oc = 3;
            for (int it = 0; it < TOPK && oc < 33; it++) {
                const int idx = topi[it];
                if (idx == ex0 || idx == ex1 || idx == ex2) continue;
                lse_buf[oc++] = topv[it] * INV_BETA;
            }
        }
        __syncwarp();
        {
            const float l0 = lse_buf[0], l1 = lse_buf[1], l2 = lse_buf[2];
            const float m2 = l0;           // global max dominates the list
            float e = 0.0f;
            if (l < 33) e += expf(lse_buf[l] - m2);
            if (l == 0) e += expf(lse_buf[32] - m2);
#pragma unroll
            for (int o = 16; o > 0; o >>= 1) e += __shfl_down_sync(0xffffffffu, e, o);
            if (l == 0) {
                float* dst = g_loss + ((size_t)h * N_ROWS + n) * 3;
                dst[0] = s_ce;
                dst[2] = m2 + logf(e) - (l0 + l1 + l2) * (1.0f / 3.0f);
            }
        }
    }
}

// ---------------- final deterministic weighted sum -------------------------------
__global__ void final_kernel(const int* __restrict__ cams, float* __restrict__ out)
{
    __shared__ double sd[N_ROWS];
    __shared__ int scams[N_ROWS];
    const int n = threadIdx.x;
    scams[n] = cams[n];
    __syncthreads();
    const int c = scams[n];
    int cnt = 0;
    for (int i = 0; i < N_ROWS; i++) cnt += (scams[i] == c);
    const double w = 1.0 / (double)cnt;
    const float* a = g_loss + (size_t)n * 3;
    const float* b = g_loss + (size_t)(N_ROWS + n) * 3;
    double t = 0.6 * ((double)a[0] + (double)b[0])
             + 0.7 * ((double)a[1] + (double)b[1])
             + 0.7 * ((double)a[2] + (double)b[2]);
    sd[n] = t * w;
    __syncthreads();
    for (int s = 256; s > 0; s >>= 1) {
        if (n < s) sd[n] += sd[n + s];
        __syncthreads();
    }
    if (n == 0) out[0] = (float)sd[0];
}

// ---------------- entry -----------------------------------------------------------
extern "C" void kernel_launch(void* const* d_in, const int* in_sizes, int n_in,
                              void* d_out, int out_size)
{
    const float* features = (const float*)d_in[0];
    const float* memory = (const float*)d_in[2];
    const int* cams  = (const int*)d_in[3];
    const int* proxy = (const int*)d_in[4];
    float* out = (float*)d_out;

    convA_k<<<(N_ROWS * D_FULL / 4) / 256, 256>>>(features);
    convB_k<<<((size_t)P_TOT * D_FULL / 4) / 256, 256>>>(memory);

    const int gsmem = 4 * (int)STG_B;   // 81920
    cudaFuncSetAttribute(gemm_mma, cudaFuncAttributeMaxDynamicSharedMemorySize, gsmem);
    dim3 ggrid(512, 2);
    gemm_mma<<<ggrid, 256, gsmem>>>();

    const int smem_bytes = P_TOT * (int)sizeof(float);
    cudaFuncSetAttribute(reduce_kernel, cudaFuncAttributeMaxDynamicSharedMemorySize,
                         smem_bytes);
    dim3 rgrid(N_ROWS, 2);
    reduce_kernel<<<rgrid, 512, smem_bytes>>>(cams, proxy);

    final_kernel<<<1, N_ROWS>>>(cams, out);
}

// round 7
// speedup vs baseline: 1.5236x; 1.1897x over previous
#include <cuda_runtime.h>
#include <cuda_bf16.h>
#include <math.h>
#include <stdint.h>

// Problem constants
#define N_ROWS   512
#define N_CAMS   8
#define M_PER    2048
#define D_FULL   4096
#define K_HALF   2048
#define P_TOT    16384
#define TOPK     54
#define INV_BETA 20.0f

// ---------------- scratch (device globals) ------------------------------------
__device__ float g_sims[2ull * N_ROWS * P_TOT];                 // 64 MB
__device__ float g_loss[2 * N_ROWS * 3];
__device__ __nv_bfloat16 g_featB[(size_t)N_ROWS * D_FULL];      // 4 MB
__device__ __nv_bfloat16 g_memB[(size_t)P_TOT * D_FULL];        // 128 MB

// ---------------- helpers ------------------------------------------------------
__device__ __forceinline__ uint32_t smem_u32(const void* p) {
    uint32_t a;
    asm("{ .reg .u64 t; cvta.to.shared.u64 t, %1; cvt.u32.u64 %0, t; }"
        : "=r"(a) : "l"(p));
    return a;
}
__device__ __forceinline__ void cp16(uint32_t s, const void* g) {
    asm volatile("cp.async.cg.shared.global [%0], [%1], 16;" :: "r"(s), "l"(g));
}
#define CP_COMMIT() asm volatile("cp.async.commit_group;" ::: "memory")

__device__ __forceinline__ void mma16(float* d, const uint32_t* a,
                                      uint32_t b0, uint32_t b1) {
    asm volatile(
        "mma.sync.aligned.m16n8k16.row.col.f32.bf16.bf16.f32 "
        "{%0,%1,%2,%3}, {%4,%5,%6,%7}, {%8,%9}, {%0,%1,%2,%3};"
        : "+f"(d[0]), "+f"(d[1]), "+f"(d[2]), "+f"(d[3])
        : "r"(a[0]), "r"(a[1]), "r"(a[2]), "r"(a[3]), "r"(b0), "r"(b1));
}

// ---------------- fp32 -> bf16 conversion --------------------------------------
__global__ void convA_k(const float* __restrict__ f) {
    size_t i = (size_t)blockIdx.x * 256 + threadIdx.x;
    float4 v = ((const float4*)f)[i];
    __nv_bfloat162 p0 = __floats2bfloat162_rn(v.x, v.y);
    __nv_bfloat162 p1 = __floats2bfloat162_rn(v.z, v.w);
    uint2 o; o.x = *(uint32_t*)&p0; o.y = *(uint32_t*)&p1;
    ((uint2*)g_featB)[i] = o;
}
__global__ void convB_k(const float* __restrict__ m) {
    size_t i = (size_t)blockIdx.x * 256 + threadIdx.x;
    float4 v = ((const float4*)m)[i];
    __nv_bfloat162 p0 = __floats2bfloat162_rn(v.x, v.y);
    __nv_bfloat162 p1 = __floats2bfloat162_rn(v.z, v.w);
    uint2 o; o.x = *(uint32_t*)&p0; o.y = *(uint32_t*)&p1;
    ((uint2*)g_memB)[i] = o;
}

// ---------------- bf16 mma.sync GEMM: 128x128 tile, 4-stage ring ---------------
#define GBK      32
#define NSTG     (K_HALF / GBK)     // 64
#define STG_B    20480u
#define ROWB     80u

__device__ __forceinline__ void load_stage(int st, int tid, int mtile, int ntile,
                                           int h, uint32_t sbase) {
    const uint32_t buf = sbase + (uint32_t)(st & 3) * STG_B;
    const int kg = h * K_HALF + st * GBK;
#pragma unroll
    for (int i = 0; i < 2; i++) {
        int idx = tid + i * 256;
        int r = idx >> 2, ch = idx & 3;
        cp16(buf + (uint32_t)r * ROWB + (uint32_t)ch * 16,
             g_featB + (size_t)(mtile * 128 + r) * D_FULL + kg + ch * 8);
    }
#pragma unroll
    for (int i = 0; i < 2; i++) {
        int idx = tid + i * 256;
        int r = idx >> 2, ch = idx & 3;
        cp16(buf + 10240u + (uint32_t)r * ROWB + (uint32_t)ch * 16,
             g_memB + (size_t)(ntile * 128 + r) * D_FULL + kg + ch * 8);
    }
    CP_COMMIT();
}

__global__ void __launch_bounds__(256, 2)
gemm_mma(void) {
    extern __shared__ char sm[];
    const uint32_t sbase = smem_u32(sm);

    const int tid = threadIdx.x;
    const int bx = blockIdx.x;
    const int h  = blockIdx.y;
    const int ntile = bx >> 2;
    const int mtile = bx & 3;

    const int w  = tid >> 5;
    const int l  = tid & 31;
    const int wm = (w & 3) * 32;
    const int wn = (w >> 2) * 64;
    const int g  = l >> 2;
    const int tg = l & 3;

    float acc[2][8][4];
#pragma unroll
    for (int mi = 0; mi < 2; mi++)
#pragma unroll
        for (int ni = 0; ni < 8; ni++)
#pragma unroll
            for (int c = 0; c < 4; c++) acc[mi][ni][c] = 0.0f;

    load_stage(0, tid, mtile, ntile, h, sbase);
    load_stage(1, tid, mtile, ntile, h, sbase);
    load_stage(2, tid, mtile, ntile, h, sbase);

    for (int st = 0; st < NSTG; st++) {
        if (st < NSTG - 2)       asm volatile("cp.async.wait_group 2;" ::: "memory");
        else if (st == NSTG - 2) asm volatile("cp.async.wait_group 1;" ::: "memory");
        else                     asm volatile("cp.async.wait_group 0;" ::: "memory");
        __syncthreads();

        if (st + 3 < NSTG) load_stage(st + 3, tid, mtile, ntile, h, sbase);

        const char* base = sm + (size_t)(st & 3) * STG_B;
#pragma unroll
        for (int ks = 0; ks < 2; ks++) {
            const int kb = ks * 32;
            uint32_t a[2][4];
#pragma unroll
            for (int mi = 0; mi < 2; mi++) {
                const char* ar = base + (wm + mi * 16 + g) * ROWB + kb + tg * 4;
                a[mi][0] = *(const uint32_t*)(ar);
                a[mi][1] = *(const uint32_t*)(ar + 8 * ROWB);
                a[mi][2] = *(const uint32_t*)(ar + 16);
                a[mi][3] = *(const uint32_t*)(ar + 8 * ROWB + 16);
            }
#pragma unroll
            for (int ni = 0; ni < 8; ni++) {
                const char* br = base + 10240 + (wn + ni * 8 + g) * ROWB + kb + tg * 4;
                uint32_t b0 = *(const uint32_t*)(br);
                uint32_t b1 = *(const uint32_t*)(br + 16);
                mma16(acc[0][ni], a[0], b0, b1);
                mma16(acc[1][ni], a[1], b0, b1);
            }
        }
    }

    const int colbase = ntile * 128 + wn;
#pragma unroll
    for (int mi = 0; mi < 2; mi++) {
        const int row = mtile * 128 + wm + mi * 16 + g;
        float* d0 = g_sims + ((size_t)(h * N_ROWS + row)) * P_TOT + colbase + tg * 2;
        float* d1 = d0 + (size_t)8 * P_TOT;
#pragma unroll
        for (int ni = 0; ni < 8; ni++) {
            *(float2*)(d0 + ni * 8) = make_float2(acc[mi][ni][0], acc[mi][ni][1]);
            *(float2*)(d1 + ni * 8) = make_float2(acc[mi][ni][2], acc[mi][ni][3]);
        }
    }
}

// ---------------- per-row loss reduction ----------------------------------------
// No smem row copy (L2 serves repeats). Rank-based parallel selection.
__device__ __forceinline__ uint32_t fkey(float v) {
    uint32_t u = __float_as_uint(v);
    return u ^ (uint32_t)(((int32_t)u >> 31) | 0x80000000);
}
__device__ __forceinline__ bool beats(float va, int ia, float vb, int ib) {
    return (va > vb) || (va == vb && ia < ib);
}

__global__ void __launch_bounds__(512, 3)
reduce_kernel(const int* __restrict__ cams, const int* __restrict__ proxy)
{
    __shared__ int   hist1[256];
    __shared__ int   hist2[256];
    __shared__ float wmax[16];
    __shared__ int   widx[16];
    __shared__ float red[16];
    __shared__ float candv[512];
    __shared__ int   candi[512];
    __shared__ float camMax[N_CAMS];
    __shared__ int   camIdx[N_CAMS];
    __shared__ float s_ce, s_rp, s_top1;
    __shared__ float s_sum1, s_sum2;
    __shared__ int   s_b1, s_above, s_count;
    __shared__ uint32_t s_thr;

    const int n = blockIdx.x;
    const int h = blockIdx.y;
    const int tid = threadIdx.x;
    const int w = tid >> 5, l = tid & 31;

    if (tid < 256) { hist1[tid] = 0; hist2[tid] = 0; }
    if (tid == 0) s_count = 0;
    __syncthreads();

    const int c = cams[n];
    const int p = proxy[n];
    const float* rowg = g_sims + ((size_t)h * N_ROWS + n) * P_TOT;
    const float4* src4 = (const float4*)rowg;

    // ---- pass 1: per-cam argmax + 8-bit histogram (gmem/L2, coalesced) ----
    const int f4base = (w >> 1) * 512 + (w & 1) * 256;
    float bv = -3.0e38f; int bi = f4base * 4;
#pragma unroll
    for (int s = 0; s < 8; s++) {
        const int f4 = f4base + s * 32 + l;
        float4 v = __ldg(&src4[f4]);
        const int j = f4 * 4;
        if (v.x > bv) { bv = v.x; bi = j; }
        if (v.y > bv) { bv = v.y; bi = j + 1; }
        if (v.z > bv) { bv = v.z; bi = j + 2; }
        if (v.w > bv) { bv = v.w; bi = j + 3; }
        float comp[4] = {v.x, v.y, v.z, v.w};
#pragma unroll
        for (int q = 0; q < 4; q++) {
            uint32_t b = fkey(comp[q]) >> 24;
            unsigned m = __match_any_sync(0xffffffffu, b);
            if ((m & ((1u << l) - 1u)) == 0) atomicAdd(&hist1[b], __popc(m));
        }
    }
#pragma unroll
    for (int o = 16; o > 0; o >>= 1) {
        float ov = __shfl_down_sync(0xffffffffu, bv, o);
        int   oi = __shfl_down_sync(0xffffffffu, bi, o);
        if (ov > bv || (ov == bv && oi < bi)) { bv = ov; bi = oi; }
    }
    if (l == 0) { wmax[w] = bv; widx[w] = bi; }
    __syncthreads();

    if (tid < N_CAMS) {
        float a = wmax[2 * tid]; int ai = widx[2 * tid];
        float b2 = wmax[2 * tid + 1]; int bi2 = widx[2 * tid + 1];
        if (b2 > a || (b2 == a && bi2 < ai)) { a = b2; ai = bi2; }
        camMax[tid] = a; camIdx[tid] = ai;
    }
    if (tid == 32) {
        int cum = 0, b = 255;
        for (; b >= 0; b--) { cum += hist1[b]; if (cum >= TOPK) break; }
        s_b1 = b; s_above = cum - hist1[b];
    }
    __syncthreads();

    // ---- pass 2: second-digit histogram + CE sum-exp (strided coalesced) ----
    const uint32_t b1 = (uint32_t)s_b1;
    const float bm = camMax[c];
    float ssum = 0.0f;
#pragma unroll
    for (int s = 0; s < 8; s++) {
        const int f4 = tid + s * 512;
        float4 v = __ldg(&src4[f4]);
        float comp[4] = {v.x, v.y, v.z, v.w};
#pragma unroll
        for (int q = 0; q < 4; q++) {
            uint32_t k = fkey(comp[q]);
            if ((k >> 24) == b1) atomicAdd(&hist2[(k >> 16) & 0xFF], 1);
        }
        if (s == c) {
            ssum += expf((v.x - bm) * INV_BETA) + expf((v.y - bm) * INV_BETA)
                  + expf((v.z - bm) * INV_BETA) + expf((v.w - bm) * INV_BETA);
        }
    }
#pragma unroll
    for (int o = 16; o > 0; o >>= 1) ssum += __shfl_down_sync(0xffffffffu, ssum, o);
    if (l == 0) red[w] = ssum;
    __syncthreads();

    if (tid == 0) {
        int cum = s_above, b = 255;
        for (; b >= 0; b--) { cum += hist2[b]; if (cum >= TOPK) break; }
        s_thr = (b1 << 24) | ((uint32_t)b << 16);
        float tot = 0.0f;
        for (int i = 0; i < 16; i++) tot += red[i];
        const float rp = __ldg(&rowg[p]);
        s_rp = rp;
        s_ce = bm * INV_BETA + logf(tot) - rp * INV_BETA;
    }
    __syncthreads();

    // ---- pass 3: gather candidates >= threshold ----
    const uint32_t thr = s_thr;
#pragma unroll
    for (int s = 0; s < 8; s++) {
        const int f4 = tid + s * 512;
        float4 v = __ldg(&src4[f4]);
        float comp[4] = {v.x, v.y, v.z, v.w};
#pragma unroll
        for (int q = 0; q < 4; q++) {
            if (fkey(comp[q]) >= thr) {
                int k = atomicAdd(&s_count, 1);
                if (k < 512) { candv[k] = comp[q]; candi[k] = f4 * 4 + q; }
            }
        }
    }
    __syncthreads();

    // ---- rank-based selection: thread k owns candidate k ----
    const int nc = (s_count < 512) ? s_count : 512;
    const bool valid = (tid < nc);
    float vk = -3.0e38f; int ik = 0x7FFFFFFF;
    if (valid) { vk = candv[tid]; ik = candi[tid]; }

    int rank = 0;
    for (int j = 0; j < nc; j++) {
        // broadcast smem reads
        float vj = candv[j]; int ij = candi[j];
        if (valid && beats(vj, ij, vk, ik)) rank++;
    }

    // top-3 cams (computed redundantly per thread from 8 smem values)
    int o0 = 0;
#pragma unroll
    for (int cc = 1; cc < N_CAMS; cc++) if (camMax[cc] > camMax[o0]) o0 = cc;
    int o1 = -1;
#pragma unroll
    for (int cc = 0; cc < N_CAMS; cc++) {
        if (cc == o0) continue;
        if (o1 < 0 || camMax[cc] > camMax[o1]) o1 = cc;
    }
    int o2 = -1;
#pragma unroll
    for (int cc = 0; cc < N_CAMS; cc++) {
        if (cc == o0 || cc == o1) continue;
        if (o2 < 0 || camMax[cc] > camMax[o2]) o2 = cc;
    }
    const float ev0 = camMax[o0], ev1 = camMax[o1], ev2 = camMax[o2];
    const int   ex0 = camIdx[o0], ex1 = camIdx[o1], ex2 = camIdx[o2];
    const float rp = s_rp;

    // the top non-proxy candidate (for assoc max): adjrank==0 && idx!=p
    const int rankNp = rank - ((valid && beats(rp, p, vk, ik)) ? 1 : 0);
    if (valid && ik != p && rankNp == 0) s_top1 = vk;
    __syncthreads();

    // ---- assoc: lse over {pos} U top-50 (proxy excluded) ----
    const float pos = rp * INV_BETA;
    const float m1 = fmaxf(pos, s_top1 * INV_BETA);
    float e1 = 0.0f;
    if (valid && ik != p && rankNp < 50) e1 = expf(vk * INV_BETA - m1);
    if (tid == 0) e1 += expf(pos - m1);

    // ---- online: lse over 3 cam-tops + top-30 of rest ----
    int rank3 = rank;
    if (valid) {
        rank3 -= (beats(ev0, ex0, vk, ik) ? 1 : 0);
        rank3 -= (beats(ev1, ex1, vk, ik) ? 1 : 0);
        rank3 -= (beats(ev2, ex2, vk, ik) ? 1 : 0);
    }
    const float m2 = ev0 * INV_BETA;   // global max
    float e2 = 0.0f;
    if (valid && ik != ex0 && ik != ex1 && ik != ex2 && rank3 < 30)
        e2 = expf(vk * INV_BETA - m2);
    if (tid == 0)
        e2 += 1.0f + expf(ev1 * INV_BETA - m2) + expf(ev2 * INV_BETA - m2);

    // block-sum e1, e2 (fixed tree)
#pragma unroll
    for (int o = 16; o > 0; o >>= 1) {
        e1 += __shfl_down_sync(0xffffffffu, e1, o);
        e2 += __shfl_down_sync(0xffffffffu, e2, o);
    }
    if (l == 0) { wmax[w] = e1; red[w] = e2; }
    __syncthreads();
    if (tid == 0) {
        float t1 = 0.0f, t2 = 0.0f;
        for (int i = 0; i < 16; i++) { t1 += wmax[i]; t2 += red[i]; }
        float* dst = g_loss + ((size_t)h * N_ROWS + n) * 3;
        dst[0] = s_ce;
        dst[1] = m1 + logf(t1) - pos;
        dst[2] = m2 + logf(t2) - (ev0 + ev1 + ev2) * INV_BETA * (1.0f / 3.0f);
    }
}

// ---------------- final deterministic weighted sum -------------------------------
__global__ void final_kernel(const int* __restrict__ cams, float* __restrict__ out)
{
    __shared__ double sd[N_ROWS];
    __shared__ int scams[N_ROWS];
    const int n = threadIdx.x;
    scams[n] = cams[n];
    __syncthreads();
    const int c = scams[n];
    int cnt = 0;
    for (int i = 0; i < N_ROWS; i++) cnt += (scams[i] == c);
    const double w = 1.0 / (double)cnt;
    const float* a = g_loss + (size_t)n * 3;
    const float* b = g_loss + (size_t)(N_ROWS + n) * 3;
    double t = 0.6 * ((double)a[0] + (double)b[0])
             + 0.7 * ((double)a[1] + (double)b[1])
             + 0.7 * ((double)a[2] + (double)b[2]);
    sd[n] = t * w;
    __syncthreads();
    for (int s = 256; s > 0; s >>= 1) {
        if (n < s) sd[n] += sd[n + s];
        __syncthreads();
    }
    if (n == 0) out[0] = (float)sd[0];
}

// ---------------- entry -----------------------------------------------------------
extern "C" void kernel_launch(void* const* d_in, const int* in_sizes, int n_in,
                              void* d_out, int out_size)
{
    const float* features = (const float*)d_in[0];
    const float* memory = (const float*)d_in[2];
    const int* cams  = (const int*)d_in[3];
    const int* proxy = (const int*)d_in[4];
    float* out = (float*)d_out;

    convA_k<<<(N_ROWS * D_FULL / 4) / 256, 256>>>(features);
    convB_k<<<((size_t)P_TOT * D_FULL / 4) / 256, 256>>>(memory);

    const int gsmem = 4 * (int)STG_B;   // 81920
    cudaFuncSetAttribute(gemm_mma, cudaFuncAttributeMaxDynamicSharedMemorySize, gsmem);
    dim3 ggrid(512, 2);
    gemm_mma<<<ggrid, 256, gsmem>>>();

    dim3 rgrid(N_ROWS, 2);
    reduce_kernel<<<rgrid, 512>>>(cams, proxy);

    final_kernel<<<1, N_ROWS>>>(cams, out);
}

// round 8
// speedup vs baseline: 1.6743x; 1.0989x over previous
#include <cuda_runtime.h>
#include <cuda_bf16.h>
#include <math.h>
#include <stdint.h>

// Problem constants
#define N_ROWS   512
#define N_CAMS   8
#define M_PER    2048
#define D_FULL   4096
#define K_HALF   2048
#define P_TOT    16384
#define TOPK     54
#define INV_BETA 20.0f

// ---------------- scratch (device globals) ------------------------------------
__device__ float g_sims[2ull * N_ROWS * P_TOT];                 // 64 MB
__device__ float g_loss[2 * N_ROWS * 3];
__device__ __nv_bfloat16 g_featB[(size_t)N_ROWS * D_FULL];      // 4 MB
__device__ __nv_bfloat16 g_memB[(size_t)P_TOT * D_FULL];        // 128 MB

// ---------------- helpers ------------------------------------------------------
__device__ __forceinline__ uint32_t smem_u32(const void* p) {
    uint32_t a;
    asm("{ .reg .u64 t; cvta.to.shared.u64 t, %1; cvt.u32.u64 %0, t; }"
        : "=r"(a) : "l"(p));
    return a;
}
__device__ __forceinline__ void cp16(uint32_t s, const void* g) {
    asm volatile("cp.async.cg.shared.global [%0], [%1], 16;" :: "r"(s), "l"(g));
}
#define CP_COMMIT() asm volatile("cp.async.commit_group;" ::: "memory")

__device__ __forceinline__ void mma16(float* d, const uint32_t* a,
                                      uint32_t b0, uint32_t b1) {
    asm volatile(
        "mma.sync.aligned.m16n8k16.row.col.f32.bf16.bf16.f32 "
        "{%0,%1,%2,%3}, {%4,%5,%6,%7}, {%8,%9}, {%0,%1,%2,%3};"
        : "+f"(d[0]), "+f"(d[1]), "+f"(d[2]), "+f"(d[3])
        : "r"(a[0]), "r"(a[1]), "r"(a[2]), "r"(a[3]), "r"(b0), "r"(b1));
}
__device__ __forceinline__ void ldsm4(uint32_t& r0, uint32_t& r1,
                                      uint32_t& r2, uint32_t& r3, uint32_t addr) {
    asm volatile("ldmatrix.sync.aligned.m8n8.x4.shared.b16 {%0,%1,%2,%3}, [%4];"
                 : "=r"(r0), "=r"(r1), "=r"(r2), "=r"(r3) : "r"(addr));
}

// ---------------- fp32 -> bf16 conversion --------------------------------------
__global__ void convA_k(const float* __restrict__ f) {
    size_t i = (size_t)blockIdx.x * 256 + threadIdx.x;
    float4 v = ((const float4*)f)[i];
    __nv_bfloat162 p0 = __floats2bfloat162_rn(v.x, v.y);
    __nv_bfloat162 p1 = __floats2bfloat162_rn(v.z, v.w);
    uint2 o; o.x = *(uint32_t*)&p0; o.y = *(uint32_t*)&p1;
    ((uint2*)g_featB)[i] = o;
}
__global__ void convB_k(const float* __restrict__ m) {
    size_t i = (size_t)blockIdx.x * 256 + threadIdx.x;
    float4 v = ((const float4*)m)[i];
    __nv_bfloat162 p0 = __floats2bfloat162_rn(v.x, v.y);
    __nv_bfloat162 p1 = __floats2bfloat162_rn(v.z, v.w);
    uint2 o; o.x = *(uint32_t*)&p0; o.y = *(uint32_t*)&p1;
    ((uint2*)g_memB)[i] = o;
}

// ---------------- bf16 mma.sync GEMM: 128x128 tile, 4-stage ring, ldmatrix -----
#define GBK      32
#define NSTG     (K_HALF / GBK)     // 64
#define STG_B    20480u
#define ROWB     80u

__device__ __forceinline__ void load_stage(int st, int tid, int mtile, int ntile,
                                           int h, uint32_t sbase) {
    const uint32_t buf = sbase + (uint32_t)(st & 3) * STG_B;
    const int kg = h * K_HALF + st * GBK;
#pragma unroll
    for (int i = 0; i < 2; i++) {
        int idx = tid + i * 256;
        int r = idx >> 2, ch = idx & 3;
        cp16(buf + (uint32_t)r * ROWB + (uint32_t)ch * 16,
             g_featB + (size_t)(mtile * 128 + r) * D_FULL + kg + ch * 8);
    }
#pragma unroll
    for (int i = 0; i < 2; i++) {
        int idx = tid + i * 256;
        int r = idx >> 2, ch = idx & 3;
        cp16(buf + 10240u + (uint32_t)r * ROWB + (uint32_t)ch * 16,
             g_memB + (size_t)(ntile * 128 + r) * D_FULL + kg + ch * 8);
    }
    CP_COMMIT();
}

__global__ void __launch_bounds__(256, 2)
gemm_mma(void) {
    extern __shared__ char sm[];
    const uint32_t sbase = smem_u32(sm);

    const int tid = threadIdx.x;
    const int bx = blockIdx.x;
    const int h  = blockIdx.y;
    const int ntile = bx >> 2;
    const int mtile = bx & 3;

    const int w  = tid >> 5;
    const int l  = tid & 31;
    const int wm = (w & 3) * 32;
    const int wn = (w >> 2) * 64;
    const int g  = l >> 2;
    const int tg = l & 3;

    // ldmatrix source offsets (within stage buffer)
    const uint32_t aOff = (uint32_t)(wm + (l & 15)) * ROWB + (uint32_t)((l >> 4) & 1) * 16;
    const uint32_t bOff = 10240u +
        (uint32_t)(wn + (l & 7) + ((l >> 4) & 1) * 8) * ROWB +
        (uint32_t)((l >> 3) & 1) * 16;

    float acc[2][8][4];
#pragma unroll
    for (int mi = 0; mi < 2; mi++)
#pragma unroll
        for (int ni = 0; ni < 8; ni++)
#pragma unroll
            for (int c = 0; c < 4; c++) acc[mi][ni][c] = 0.0f;

    load_stage(0, tid, mtile, ntile, h, sbase);
    load_stage(1, tid, mtile, ntile, h, sbase);
    load_stage(2, tid, mtile, ntile, h, sbase);

    for (int st = 0; st < NSTG; st++) {
        if (st < NSTG - 2)       asm volatile("cp.async.wait_group 2;" ::: "memory");
        else if (st == NSTG - 2) asm volatile("cp.async.wait_group 1;" ::: "memory");
        else                     asm volatile("cp.async.wait_group 0;" ::: "memory");
        __syncthreads();

        if (st + 3 < NSTG) load_stage(st + 3, tid, mtile, ntile, h, sbase);

        const uint32_t stg = sbase + (uint32_t)(st & 3) * STG_B;
        const uint32_t aBase = stg + aOff;
        const uint32_t bBase = stg + bOff;

#pragma unroll
        for (int ks = 0; ks < 2; ks++) {
            const uint32_t kb = (uint32_t)ks * 32;
            uint32_t a[2][4];
            ldsm4(a[0][0], a[0][1], a[0][2], a[0][3], aBase + kb);
            ldsm4(a[1][0], a[1][1], a[1][2], a[1][3], aBase + kb + 16 * ROWB);
            uint32_t bb[4][4];
#pragma unroll
            for (int np = 0; np < 4; np++)
                ldsm4(bb[np][0], bb[np][1], bb[np][2], bb[np][3],
                      bBase + kb + (uint32_t)np * 16 * ROWB);
#pragma unroll
            for (int ni = 0; ni < 8; ni++) {
                const uint32_t b0 = bb[ni >> 1][(ni & 1) * 2];
                const uint32_t b1 = bb[ni >> 1][(ni & 1) * 2 + 1];
                mma16(acc[0][ni], a[0], b0, b1);
                mma16(acc[1][ni], a[1], b0, b1);
            }
        }
    }

    const int colbase = ntile * 128 + wn;
#pragma unroll
    for (int mi = 0; mi < 2; mi++) {
        const int row = mtile * 128 + wm + mi * 16 + g;
        float* d0 = g_sims + ((size_t)(h * N_ROWS + row)) * P_TOT + colbase + tg * 2;
        float* d1 = d0 + (size_t)8 * P_TOT;
#pragma unroll
        for (int ni = 0; ni < 8; ni++) {
            *(float2*)(d0 + ni * 8) = make_float2(acc[mi][ni][0], acc[mi][ni][1]);
            *(float2*)(d1 + ni * 8) = make_float2(acc[mi][ni][2], acc[mi][ni][3]);
        }
    }
}

// ---------------- per-row loss reduction ----------------------------------------
__device__ __forceinline__ uint32_t fkey(float v) {
    uint32_t u = __float_as_uint(v);
    return u ^ (uint32_t)(((int32_t)u >> 31) | 0x80000000);
}
__device__ __forceinline__ bool beats(float va, int ia, float vb, int ib) {
    return (va > vb) || (va == vb && ia < ib);
}

__global__ void __launch_bounds__(512, 3)
reduce_kernel(const int* __restrict__ cams, const int* __restrict__ proxy)
{
    __shared__ int   hist1[256];
    __shared__ int   hist2[256];
    __shared__ float wmax[16];
    __shared__ int   widx[16];
    __shared__ float red[16];
    __shared__ float candv[512];
    __shared__ int   candi[512];
    __shared__ float camMax[N_CAMS];
    __shared__ int   camIdx[N_CAMS];
    __shared__ float s_ce, s_rp, s_top1;
    __shared__ int   s_b1, s_above, s_count;
    __shared__ uint32_t s_thr;

    const int n = blockIdx.x;
    const int h = blockIdx.y;
    const int tid = threadIdx.x;
    const int w = tid >> 5, l = tid & 31;

    if (tid < 256) { hist1[tid] = 0; hist2[tid] = 0; }
    if (tid == 0) s_count = 0;
    __syncthreads();

    const int c = cams[n];
    const int p = proxy[n];
    const float* rowg = g_sims + ((size_t)h * N_ROWS + n) * P_TOT;
    const float4* src4 = (const float4*)rowg;

    // ---- pass 1: per-cam argmax + 8-bit histogram ----
    const int f4base = (w >> 1) * 512 + (w & 1) * 256;
    float bv = -3.0e38f; int bi = f4base * 4;
#pragma unroll
    for (int s = 0; s < 8; s++) {
        const int f4 = f4base + s * 32 + l;
        float4 v = __ldg(&src4[f4]);
        const int j = f4 * 4;
        if (v.x > bv) { bv = v.x; bi = j; }
        if (v.y > bv) { bv = v.y; bi = j + 1; }
        if (v.z > bv) { bv = v.z; bi = j + 2; }
        if (v.w > bv) { bv = v.w; bi = j + 3; }
        float comp[4] = {v.x, v.y, v.z, v.w};
#pragma unroll
        for (int q = 0; q < 4; q++) {
            uint32_t b = fkey(comp[q]) >> 24;
            unsigned m = __match_any_sync(0xffffffffu, b);
            if ((m & ((1u << l) - 1u)) == 0) atomicAdd(&hist1[b], __popc(m));
        }
    }
#pragma unroll
    for (int o = 16; o > 0; o >>= 1) {
        float ov = __shfl_down_sync(0xffffffffu, bv, o);
        int   oi = __shfl_down_sync(0xffffffffu, bi, o);
        if (ov > bv || (ov == bv && oi < bi)) { bv = ov; bi = oi; }
    }
    if (l == 0) { wmax[w] = bv; widx[w] = bi; }
    __syncthreads();

    if (tid < N_CAMS) {
        float a = wmax[2 * tid]; int ai = widx[2 * tid];
        float b2 = wmax[2 * tid + 1]; int bi2 = widx[2 * tid + 1];
        if (b2 > a || (b2 == a && bi2 < ai)) { a = b2; ai = bi2; }
        camMax[tid] = a; camIdx[tid] = ai;
    }
    if (tid == 32) {
        int cum = 0, b = 255;
        for (; b >= 0; b--) { cum += hist1[b]; if (cum >= TOPK) break; }
        s_b1 = b; s_above = cum - hist1[b];
    }
    __syncthreads();

    // ---- pass 2: second-digit histogram + CE sum-exp ----
    const uint32_t b1 = (uint32_t)s_b1;
    const float bm = camMax[c];
    float ssum = 0.0f;
#pragma unroll
    for (int s = 0; s < 8; s++) {
        const int f4 = tid + s * 512;
        float4 v = __ldg(&src4[f4]);
        float comp[4] = {v.x, v.y, v.z, v.w};
#pragma unroll
        for (int q = 0; q < 4; q++) {
            uint32_t k = fkey(comp[q]);
            if ((k >> 24) == b1) atomicAdd(&hist2[(k >> 16) & 0xFF], 1);
        }
        if (s == c) {
            ssum += expf((v.x - bm) * INV_BETA) + expf((v.y - bm) * INV_BETA)
                  + expf((v.z - bm) * INV_BETA) + expf((v.w - bm) * INV_BETA);
        }
    }
#pragma unroll
    for (int o = 16; o > 0; o >>= 1) ssum += __shfl_down_sync(0xffffffffu, ssum, o);
    if (l == 0) red[w] = ssum;
    __syncthreads();

    if (tid == 0) {
        int cum = s_above, b = 255;
        for (; b >= 0; b--) { cum += hist2[b]; if (cum >= TOPK) break; }
        s_thr = (b1 << 24) | ((uint32_t)b << 16);
        float tot = 0.0f;
        for (int i = 0; i < 16; i++) tot += red[i];
        const float rp = __ldg(&rowg[p]);
        s_rp = rp;
        s_ce = bm * INV_BETA + logf(tot) - rp * INV_BETA;
    }
    __syncthreads();

    // ---- pass 3: gather candidates >= threshold ----
    const uint32_t thr = s_thr;
#pragma unroll
    for (int s = 0; s < 8; s++) {
        const int f4 = tid + s * 512;
        float4 v = __ldg(&src4[f4]);
        float comp[4] = {v.x, v.y, v.z, v.w};
#pragma unroll
        for (int q = 0; q < 4; q++) {
            if (fkey(comp[q]) >= thr) {
                int k = atomicAdd(&s_count, 1);
                if (k < 512) { candv[k] = comp[q]; candi[k] = f4 * 4 + q; }
            }
        }
    }
    __syncthreads();

    // ---- rank-based selection: thread k owns candidate k ----
    const int nc = (s_count < 512) ? s_count : 512;
    const bool valid = (tid < nc);
    float vk = -3.0e38f; int ik = 0x7FFFFFFF;
    if (valid) { vk = candv[tid]; ik = candi[tid]; }

    int rank = 0;
    for (int j = 0; j < nc; j++) {
        float vj = candv[j]; int ij = candi[j];
        if (valid && beats(vj, ij, vk, ik)) rank++;
    }

    int o0 = 0;
#pragma unroll
    for (int cc = 1; cc < N_CAMS; cc++) if (camMax[cc] > camMax[o0]) o0 = cc;
    int o1 = -1;
#pragma unroll
    for (int cc = 0; cc < N_CAMS; cc++) {
        if (cc == o0) continue;
        if (o1 < 0 || camMax[cc] > camMax[o1]) o1 = cc;
    }
    int o2 = -1;
#pragma unroll
    for (int cc = 0; cc < N_CAMS; cc++) {
        if (cc == o0 || cc == o1) continue;
        if (o2 < 0 || camMax[cc] > camMax[o2]) o2 = cc;
    }
    const float ev0 = camMax[o0], ev1 = camMax[o1], ev2 = camMax[o2];
    const int   ex0 = camIdx[o0], ex1 = camIdx[o1], ex2 = camIdx[o2];
    const float rp = s_rp;

    const int rankNp = rank - ((valid && beats(rp, p, vk, ik)) ? 1 : 0);
    if (valid && ik != p && rankNp == 0) s_top1 = vk;
    __syncthreads();

    const float pos = rp * INV_BETA;
    const float m1 = fmaxf(pos, s_top1 * INV_BETA);
    float e1 = 0.0f;
    if (valid && ik != p && rankNp < 50) e1 = expf(vk * INV_BETA - m1);
    if (tid == 0) e1 += expf(pos - m1);

    int rank3 = rank;
    if (valid) {
        rank3 -= (beats(ev0, ex0, vk, ik) ? 1 : 0);
        rank3 -= (beats(ev1, ex1, vk, ik) ? 1 : 0);
        rank3 -= (beats(ev2, ex2, vk, ik) ? 1 : 0);
    }
    const float m2 = ev0 * INV_BETA;
    float e2 = 0.0f;
    if (valid && ik != ex0 && ik != ex1 && ik != ex2 && rank3 < 30)
        e2 = expf(vk * INV_BETA - m2);
    if (tid == 0)
        e2 += 1.0f + expf(ev1 * INV_BETA - m2) + expf(ev2 * INV_BETA - m2);

#pragma unroll
    for (int o = 16; o > 0; o >>= 1) {
        e1 += __shfl_down_sync(0xffffffffu, e1, o);
        e2 += __shfl_down_sync(0xffffffffu, e2, o);
    }
    if (l == 0) { wmax[w] = e1; red[w] = e2; }
    __syncthreads();
    if (tid == 0) {
        float t1 = 0.0f, t2 = 0.0f;
        for (int i = 0; i < 16; i++) { t1 += wmax[i]; t2 += red[i]; }
        float* dst = g_loss + ((size_t)h * N_ROWS + n) * 3;
        dst[0] = s_ce;
        dst[1] = m1 + logf(t1) - pos;
        dst[2] = m2 + logf(t2) - (ev0 + ev1 + ev2) * INV_BETA * (1.0f / 3.0f);
    }
}

// ---------------- final deterministic weighted sum -------------------------------
__global__ void final_kernel(const int* __restrict__ cams, float* __restrict__ out)
{
    __shared__ double sd[N_ROWS];
    __shared__ int scams[N_ROWS];
    const int n = threadIdx.x;
    scams[n] = cams[n];
    __syncthreads();
    const int c = scams[n];
    int cnt = 0;
    for (int i = 0; i < N_ROWS; i++) cnt += (scams[i] == c);
    const double w = 1.0 / (double)cnt;
    const float* a = g_loss + (size_t)n * 3;
    const float* b = g_loss + (size_t)(N_ROWS + n) * 3;
    double t = 0.6 * ((double)a[0] + (double)b[0])
             + 0.7 * ((double)a[1] + (double)b[1])
             + 0.7 * ((double)a[2] + (double)b[2]);
    sd[n] = t * w;
    __syncthreads();
    for (int s = 256; s > 0; s >>= 1) {
        if (n < s) sd[n] += sd[n + s];
        __syncthreads();
    }
    if (n == 0) out[0] = (float)sd[0];
}

// ---------------- entry -----------------------------------------------------------
extern "C" void kernel_launch(void* const* d_in, const int* in_sizes, int n_in,
                              void* d_out, int out_size)
{
    const float* features = (const float*)d_in[0];
    const float* memory = (const float*)d_in[2];
    const int* cams  = (const int*)d_in[3];
    const int* proxy = (const int*)d_in[4];
    float* out = (float*)d_out;

    convA_k<<<(N_ROWS * D_FULL / 4) / 256, 256>>>(features);
    convB_k<<<((size_t)P_TOT * D_FULL / 4) / 256, 256>>>(memory);

    const int gsmem = 4 * (int)STG_B;   // 81920
    cudaFuncSetAttribute(gemm_mma, cudaFuncAttributeMaxDynamicSharedMemorySize, gsmem);
    dim3 ggrid(512, 2);
    gemm_mma<<<ggrid, 256, gsmem>>>();

    dim3 rgrid(N_ROWS, 2);
    reduce_kernel<<<rgrid, 512>>>(cams, proxy);

    final_kernel<<<1, N_ROWS>>>(cams, out);
}